// round 6
// baseline (speedup 1.0000x reference)
#include <cuda_runtime.h>
#include <cstdint>

// ---------------- problem constants ----------------
#define NROWS   8192
#define KDIM    4096
#define ODIM    4096
#define KW      128                 // total 32-bit sign words per row
#define KWX     96                  // k-words handled by XNOR warps
#define KHEAD   (KWX * 32)          // 3072
#define K8      1024                // s8 tail bytes handled by IMMA warps
#define TW      128                 // output tile 128 x 128
#define CHUNK   16                  // XNOR k-words per stage
#define KITX    (KWX / CHUNK)       // 6
#define KITI    (K8 / 128)          // 8
// smem: XNOR stages [0,64K) (also combine buffer), IMMA stages [64K,160K)
#define XST_WORDS 4096              // 16KB per XNOR stage
#define IS_BASE   65536
#define IST_BYTES 32768
#define SMEM_BYTES (IS_BASE + 3 * IST_BYTES)   // 163840

// ---------------- device scratch (allocation-free rule) ----------------
__device__ __align__(1024) uint32_t g_xT[(size_t)KW * NROWS];  // bit planes [kw][n]
__device__ __align__(1024) uint32_t g_wT[(size_t)KW * ODIM];
__device__ __align__(1024) uint8_t  g_x8[(size_t)NROWS * K8];  // s8 tail [n][1024]
__device__ __align__(1024) uint8_t  g_w8[(size_t)ODIM * K8];

// ---------------- helpers ----------------
__device__ __forceinline__ uint32_t smem_u32(const void* p) {
    uint32_t a;
    asm("{ .reg .u64 t; cvta.to.shared.u64 t, %1; cvt.u32.u64 %0, t; }" : "=r"(a) : "l"(p));
    return a;
}
#define CP_ASYNC16(dst, src) \
    asm volatile("cp.async.cg.shared.global [%0], [%1], 16;" :: "r"(dst), "l"(src))
#define CP_COMMIT() asm volatile("cp.async.commit_group;" ::: "memory")
#define CP_WAIT(n)  asm volatile("cp.async.wait_group %0;" :: "n"(n) : "memory")
#define BAR(id)     asm volatile("bar.sync %0, 256;" :: "r"(id) : "memory")

__device__ __forceinline__ void ldsm4(uint32_t* r, uint32_t addr) {
    asm volatile("ldmatrix.sync.aligned.m8n8.x4.shared.b16 {%0,%1,%2,%3}, [%4];"
        : "=r"(r[0]), "=r"(r[1]), "=r"(r[2]), "=r"(r[3]) : "r"(addr));
}
__device__ __forceinline__ void mma_s8(int* d, const uint32_t* a,
                                       uint32_t b0, uint32_t b1) {
    asm volatile("mma.sync.aligned.m16n8k32.row.col.s32.s8.s8.s32 "
        "{%0,%1,%2,%3}, {%4,%5,%6,%7}, {%8,%9}, {%0,%1,%2,%3};"
        : "+r"(d[0]), "+r"(d[1]), "+r"(d[2]), "+r"(d[3])
        : "r"(a[0]), "r"(a[1]), "r"(a[2]), "r"(a[3]), "r"(b0), "r"(b1));
}
__device__ __forceinline__ uint32_t sgnb(uint32_t v) {
    return (uint32_t)((((int32_t)v) >> 31) | 1) & 0xFFu;   // +1 or 0xFF(-1)
}

// ---------------- pack: f32 -> bit planes [kw][n]; tail kw>=96 also s8 ---
__global__ void __launch_bounds__(256) pack_bits2(const float4* __restrict__ in,
                                                  uint32_t* __restrict__ outT,
                                                  uint8_t* __restrict__ out8,
                                                  int nShift) {
    const int idx = blockIdx.x * 256 + threadIdx.x;
    const int n   = idx & ((1 << nShift) - 1);
    const int kw  = idx >> nShift;
    const float4* p = in + (size_t)n * (KDIM / 4) + kw * 8;
    float4 v[8];
    #pragma unroll
    for (int j = 0; j < 8; j++) v[j] = p[j];
    uint32_t w = 0;
    #pragma unroll
    for (int j = 0; j < 8; j++) {
        w |= (__float_as_uint(v[j].x) >> 31) << (4 * j);
        w |= (__float_as_uint(v[j].y) >> 31) << (4 * j + 1);
        w |= (__float_as_uint(v[j].z) >> 31) << (4 * j + 2);
        w |= (__float_as_uint(v[j].w) >> 31) << (4 * j + 3);
    }
    outT[idx] = w;
    if (kw >= KWX) {
        uint32_t b[8];
        #pragma unroll
        for (int j = 0; j < 8; j++)
            b[j] = sgnb(__float_as_uint(v[j].x))
                 | (sgnb(__float_as_uint(v[j].y)) << 8)
                 | (sgnb(__float_as_uint(v[j].z)) << 16)
                 | (sgnb(__float_as_uint(v[j].w)) << 24);
        uint8_t* d = out8 + (size_t)n * K8 + (kw - KWX) * 32;
        *reinterpret_cast<uint4*>(d)      = make_uint4(b[0], b[1], b[2], b[3]);
        *reinterpret_cast<uint4*>(d + 16) = make_uint4(b[4], b[5], b[6], b[7]);
    }
}

// ---------------- hybrid XNOR(alu) + IMMA(tensor) GEMM ----------------
__global__ void __launch_bounds__(512, 1) hybrid_gemm(
    const uint32_t* __restrict__ xT, const uint32_t* __restrict__ wT,
    const uint8_t* __restrict__ x8, const uint8_t* __restrict__ w8,
    const float* __restrict__ bias, float* __restrict__ out)
{
    extern __shared__ __align__(16) uint32_t sm[];
    const uint32_t smBase = smem_u32(sm);
    const int tid = threadIdx.x;
    const int mt  = blockIdx.x & 63;
    const int nt  = blockIdx.x >> 6;
    const int mBase = mt * TW;
    const int nBase = nt * TW;

    if (tid < 256) {
        // ===================== XNOR group: k-words [0,96) =====================
        const int t  = tid;
        const int tx = t & 15;
        const int ty = t >> 4;

        auto loadX = [&](int s, int c) {
            #pragma unroll
            for (int k = 0; k < 4; k++) {
                const int ch  = t + k * 256;
                const int tsr = ch >> 9;
                const int rem = ch & 511;
                const int kw  = rem >> 5;
                const int nq  = rem & 31;
                const uint32_t* gsrc = tsr
                    ? (wT + (size_t)(c * CHUNK + kw) * ODIM  + nBase + nq * 4)
                    : (xT + (size_t)(c * CHUNK + kw) * NROWS + mBase + nq * 4);
                const uint32_t dst = smBase +
                    (uint32_t)((s * XST_WORDS + tsr * 2048 + kw * TW + nq * 4) * 4);
                CP_ASYNC16(dst, gsrc);
            }
        };

        int acc[8][8];
        #pragma unroll
        for (int r = 0; r < 8; r++)
            #pragma unroll
            for (int c = 0; c < 8; c++) acc[r][c] = 0;

        #pragma unroll
        for (int s = 0; s < 3; s++) { loadX(s, s); CP_COMMIT(); }

        #pragma unroll 1
        for (int c = 0; c < KITX; c++) {
            const int cl = c + 3;
            if (cl < KITX) loadX(cl & 3, cl);
            CP_COMMIT();
            CP_WAIT(3);
            BAR(1);

            const uint32_t* As = sm + (c & 3) * XST_WORDS;
            const uint32_t* Bs = As + 2048;

            #pragma unroll 1
            for (int kw = 0; kw < CHUNK; kw += 2) {
                uint4 a00 = *reinterpret_cast<const uint4*>(As + kw * TW + ty * 8);
                uint4 a01 = *reinterpret_cast<const uint4*>(As + kw * TW + ty * 8 + 4);
                uint4 a10 = *reinterpret_cast<const uint4*>(As + (kw + 1) * TW + ty * 8);
                uint4 a11 = *reinterpret_cast<const uint4*>(As + (kw + 1) * TW + ty * 8 + 4);
                uint4 b00 = *reinterpret_cast<const uint4*>(Bs + kw * TW + tx * 8);
                uint4 b01 = *reinterpret_cast<const uint4*>(Bs + kw * TW + tx * 8 + 4);
                uint4 b10 = *reinterpret_cast<const uint4*>(Bs + (kw + 1) * TW + tx * 8);
                uint4 b11 = *reinterpret_cast<const uint4*>(Bs + (kw + 1) * TW + tx * 8 + 4);

                uint32_t A0[8] = {a00.x, a00.y, a00.z, a00.w, a01.x, a01.y, a01.z, a01.w};
                uint32_t A1[8] = {a10.x, a10.y, a10.z, a10.w, a11.x, a11.y, a11.z, a11.w};
                uint32_t B0[8] = {b00.x, b00.y, b00.z, b00.w, b01.x, b01.y, b01.z, b01.w};
                uint32_t B1[8] = {b10.x, b10.y, b10.z, b10.w, b11.x, b11.y, b11.z, b11.w};

                #pragma unroll
                for (int r = 0; r < 8; r++)
                    #pragma unroll
                    for (int cc = 0; cc < 8; cc++)
                        acc[r][cc] += __popc(A0[r] ^ B0[cc]) + __popc(A1[r] ^ B1[cc]);
            }
            BAR(1);
        }

        __syncthreads();   // join #1: IMMA group done; stages reusable
        __syncthreads();   // join #2: IMMA partials in smem [0,64K)

        // -------- epilogue: head + tail + bias --------
        const int rb = mBase + ty * 8;
        const int cb = nBase + tx * 8;
        const float4 bias0 = *reinterpret_cast<const float4*>(bias + cb);
        const float4 bias1 = *reinterpret_cast<const float4*>(bias + cb + 4);
        const int* smC = reinterpret_cast<const int*>(sm);

        #pragma unroll
        for (int r = 0; r < 8; r++) {
            int4 p0 = *reinterpret_cast<const int4*>(smC + (ty * 8 + r) * TW + tx * 8);
            int4 p1 = *reinterpret_cast<const int4*>(smC + (ty * 8 + r) * TW + tx * 8 + 4);
            float4 o0, o1;
            o0.x = (float)(KHEAD - 2 * acc[r][0] + p0.x) + bias0.x;
            o0.y = (float)(KHEAD - 2 * acc[r][1] + p0.y) + bias0.y;
            o0.z = (float)(KHEAD - 2 * acc[r][2] + p0.z) + bias0.z;
            o0.w = (float)(KHEAD - 2 * acc[r][3] + p0.w) + bias0.w;
            o1.x = (float)(KHEAD - 2 * acc[r][4] + p1.x) + bias1.x;
            o1.y = (float)(KHEAD - 2 * acc[r][5] + p1.y) + bias1.y;
            o1.z = (float)(KHEAD - 2 * acc[r][6] + p1.z) + bias1.z;
            o1.w = (float)(KHEAD - 2 * acc[r][7] + p1.w) + bias1.w;
            float* po = out + (size_t)(rb + r) * ODIM + cb;
            *reinterpret_cast<float4*>(po)     = o0;
            *reinterpret_cast<float4*>(po + 4) = o1;
        }
    } else {
        // ===================== IMMA group: s8 tail K=1024 =====================
        const int t2   = tid - 256;
        const int w2   = t2 >> 5;          // 0..7: 2(m) x 4(n)
        const int lane = t2 & 31;
        const int wm   = (w2 & 1) * 64;
        const int wn   = (w2 >> 1) * 32;

        auto loadI = [&](int s, int kit) {
            #pragma unroll
            for (int k = 0; k < 8; k++) {
                const int ch  = t2 + k * 256;      // 0..2047
                const int tsr = ch >> 10;
                const int rem = ch & 1023;
                const int row = rem >> 3;
                const int c16 = rem & 7;
                const uint8_t* gsrc = tsr
                    ? (w8 + (size_t)(nBase + row) * K8 + kit * 128 + c16 * 16)
                    : (x8 + (size_t)(mBase + row) * K8 + kit * 128 + c16 * 16);
                const uint32_t dst = smBase + IS_BASE + s * IST_BYTES + tsr * 16384
                    + row * 128 + (((uint32_t)(c16 * 16)) ^ ((row & 7) << 4));
                CP_ASYNC16(dst, gsrc);
            }
        };

        // ldmatrix per-thread offsets (proven layout from int8 rounds)
        const int rA = wm + (lane & 7) + ((lane >> 3) & 1) * 8;
        const int cA = ((lane >> 4) & 1) * 16;
        const uint32_t swzA = (uint32_t)((rA & 7) << 4);
        const int rB = wn + (lane & 7) + ((lane >> 4) & 1) * 8;
        const int cB = ((lane >> 3) & 1) * 16;
        const uint32_t swzB = (uint32_t)((rB & 7) << 4);

        int acc[4][4][4];
        #pragma unroll
        for (int mi = 0; mi < 4; mi++)
            #pragma unroll
            for (int ni = 0; ni < 4; ni++)
                #pragma unroll
                for (int q = 0; q < 4; q++) acc[mi][ni][q] = 0;

        loadI(0, 0); CP_COMMIT();
        loadI(1, 1); CP_COMMIT();

        #pragma unroll 1
        for (int kit = 0; kit < KITI; kit++) {
            const int s = kit % 3;
            CP_WAIT(1);
            BAR(2);

            const uint32_t sA = smBase + IS_BASE + s * IST_BYTES + rA * 128;
            const uint32_t sB = smBase + IS_BASE + s * IST_BYTES + 16384 + rB * 128;

            #pragma unroll
            for (int ks = 0; ks < 4; ks++) {
                uint32_t aF[4][4];
                uint32_t bF[2][4];
                #pragma unroll
                for (int mi = 0; mi < 4; mi++)
                    ldsm4(aF[mi], sA + mi * (16 * 128) + (((uint32_t)(cA + ks * 32)) ^ swzA));
                #pragma unroll
                for (int np = 0; np < 2; np++)
                    ldsm4(bF[np], sB + np * (16 * 128) + (((uint32_t)(cB + ks * 32)) ^ swzB));
                #pragma unroll
                for (int ni = 0; ni < 4; ni++)
                    #pragma unroll
                    for (int mi = 0; mi < 4; mi++)
                        mma_s8(acc[mi][ni], aF[mi], bF[ni >> 1][(ni & 1) * 2],
                                                     bF[ni >> 1][(ni & 1) * 2 + 1]);
            }
            BAR(2);

            const int kl = kit + 2;
            if (kl < KITI) loadI(kl % 3, kl);
            CP_COMMIT();
        }

        __syncthreads();   // join #1: XNOR done reading its stages

        // write s32 partials into combine buffer [0,64K)
        int* smC = reinterpret_cast<int*>(sm);
        const int colL = wn + (lane & 3) * 2;
        const int rowB = wm + (lane >> 2);
        #pragma unroll
        for (int mi = 0; mi < 4; mi++) {
            const int r0 = rowB + mi * 16;
            #pragma unroll
            for (int ni = 0; ni < 4; ni++) {
                *reinterpret_cast<int2*>(smC + r0 * TW + colL + ni * 8) =
                    make_int2(acc[mi][ni][0], acc[mi][ni][1]);
                *reinterpret_cast<int2*>(smC + (r0 + 8) * TW + colL + ni * 8) =
                    make_int2(acc[mi][ni][2], acc[mi][ni][3]);
            }
        }
        __syncthreads();   // join #2: partials visible to XNOR epilogue
    }
}

// ---------------- host ----------------
extern "C" void kernel_launch(void* const* d_in, const int* in_sizes, int n_in,
                              void* d_out, int out_size) {
    const float* x    = (const float*)d_in[0];
    const float* w    = (const float*)d_in[1];
    const float* bias = (const float*)d_in[2];
    float* out = (float*)d_out;

    void* pxT = nullptr; cudaGetSymbolAddress(&pxT, g_xT);
    void* pwT = nullptr; cudaGetSymbolAddress(&pwT, g_wT);
    void* px8 = nullptr; cudaGetSymbolAddress(&px8, g_x8);
    void* pw8 = nullptr; cudaGetSymbolAddress(&pw8, g_w8);

    pack_bits2<<<(KW * NROWS) / 256, 256>>>((const float4*)x, (uint32_t*)pxT,
                                            (uint8_t*)px8, 13);
    pack_bits2<<<(KW * ODIM) / 256, 256>>>((const float4*)w, (uint32_t*)pwT,
                                           (uint8_t*)pw8, 12);

    cudaFuncSetAttribute(hybrid_gemm, cudaFuncAttributeMaxDynamicSharedMemorySize,
                         SMEM_BYTES);

    const int grid = (NROWS / TW) * (ODIM / TW);   // 2048
    hybrid_gemm<<<grid, 512, SMEM_BYTES>>>((const uint32_t*)pxT, (const uint32_t*)pwT,
                                           (const uint8_t*)px8, (const uint8_t*)pw8,
                                           bias, out);
}

// round 7
// speedup vs baseline: 1.0729x; 1.0729x over previous
#include <cuda_runtime.h>
#include <cstdint>

// ---------------- problem constants ----------------
#define NROWS   8192
#define KDIM    4096
#define ODIM    4096
#define KW      128                 // total 32-bit sign words per row
#define KWX     96                  // k-words handled by XNOR warps
#define KHEAD   (KWX * 32)          // 3072
#define K8      1024                // s8 tail bytes handled by IMMA warps
#define TW      128                 // output tile 128 x 128
#define CHUNK   16                  // XNOR k-words per stage
#define KITX    (KWX / CHUNK)       // 6
#define KITI    (K8 / 128)          // 8
// smem: XNOR stages [0,64K) (also combine buffer), IMMA stages [64K,160K)
#define XST_WORDS 4096              // 16KB per XNOR stage
#define IS_BASE   65536
#define IST_BYTES 32768
#define SMEM_BYTES (IS_BASE + 3 * IST_BYTES)   // 163840

// ---------------- device scratch (allocation-free rule) ----------------
__device__ __align__(1024) uint32_t g_xT[(size_t)KW * NROWS];  // bit planes [kw][n]
__device__ __align__(1024) uint32_t g_wT[(size_t)KW * ODIM];
__device__ __align__(1024) uint8_t  g_x8[(size_t)NROWS * K8];  // s8 tail [n][1024]
__device__ __align__(1024) uint8_t  g_w8[(size_t)ODIM * K8];

// ---------------- helpers ----------------
__device__ __forceinline__ uint32_t smem_u32(const void* p) {
    uint32_t a;
    asm("{ .reg .u64 t; cvta.to.shared.u64 t, %1; cvt.u32.u64 %0, t; }" : "=r"(a) : "l"(p));
    return a;
}
#define CP_ASYNC16(dst, src) \
    asm volatile("cp.async.cg.shared.global [%0], [%1], 16;" :: "r"(dst), "l"(src))
#define CP_COMMIT() asm volatile("cp.async.commit_group;" ::: "memory")
#define CP_WAIT(n)  asm volatile("cp.async.wait_group %0;" :: "n"(n) : "memory")
#define BAR(id)     asm volatile("bar.sync %0, 256;" :: "r"(id) : "memory")

__device__ __forceinline__ void ldsm4(uint32_t* r, uint32_t addr) {
    asm volatile("ldmatrix.sync.aligned.m8n8.x4.shared.b16 {%0,%1,%2,%3}, [%4];"
        : "=r"(r[0]), "=r"(r[1]), "=r"(r[2]), "=r"(r[3]) : "r"(addr));
}
__device__ __forceinline__ void mma_s8(int* d, const uint32_t* a,
                                       uint32_t b0, uint32_t b1) {
    asm volatile("mma.sync.aligned.m16n8k32.row.col.s32.s8.s8.s32 "
        "{%0,%1,%2,%3}, {%4,%5,%6,%7}, {%8,%9}, {%0,%1,%2,%3};"
        : "+r"(d[0]), "+r"(d[1]), "+r"(d[2]), "+r"(d[3])
        : "r"(a[0]), "r"(a[1]), "r"(a[2]), "r"(a[3]), "r"(b0), "r"(b1));
}
__device__ __forceinline__ uint32_t sgnb(uint32_t v) {
    return (uint32_t)((((int32_t)v) >> 31) | 1) & 0xFFu;   // +1 or 0xFF(-1)
}
__device__ __forceinline__ uint32_t xor3(uint32_t a, uint32_t b, uint32_t c) {
    uint32_t d; asm("lop3.b32 %0, %1, %2, %3, 0x96;" : "=r"(d) : "r"(a), "r"(b), "r"(c));
    return d;
}
__device__ __forceinline__ uint32_t maj3(uint32_t a, uint32_t b, uint32_t c) {
    uint32_t d; asm("lop3.b32 %0, %1, %2, %3, 0xE8;" : "=r"(d) : "r"(a), "r"(b), "r"(c));
    return d;
}

// ---------------- pack: f32 -> bit planes [kw][n]; tail kw>=96 also s8 ---
__global__ void __launch_bounds__(256) pack_bits2(const float4* __restrict__ in,
                                                  uint32_t* __restrict__ outT,
                                                  uint8_t* __restrict__ out8,
                                                  int nShift) {
    const int idx = blockIdx.x * 256 + threadIdx.x;
    const int n   = idx & ((1 << nShift) - 1);
    const int kw  = idx >> nShift;
    const float4* p = in + (size_t)n * (KDIM / 4) + kw * 8;
    float4 v[8];
    #pragma unroll
    for (int j = 0; j < 8; j++) v[j] = p[j];
    uint32_t w = 0;
    #pragma unroll
    for (int j = 0; j < 8; j++) {
        w |= (__float_as_uint(v[j].x) >> 31) << (4 * j);
        w |= (__float_as_uint(v[j].y) >> 31) << (4 * j + 1);
        w |= (__float_as_uint(v[j].z) >> 31) << (4 * j + 2);
        w |= (__float_as_uint(v[j].w) >> 31) << (4 * j + 3);
    }
    outT[idx] = w;
    if (kw >= KWX) {
        uint32_t b[8];
        #pragma unroll
        for (int j = 0; j < 8; j++)
            b[j] = sgnb(__float_as_uint(v[j].x))
                 | (sgnb(__float_as_uint(v[j].y)) << 8)
                 | (sgnb(__float_as_uint(v[j].z)) << 16)
                 | (sgnb(__float_as_uint(v[j].w)) << 24);
        uint8_t* d = out8 + (size_t)n * K8 + (kw - KWX) * 32;
        *reinterpret_cast<uint4*>(d)      = make_uint4(b[0], b[1], b[2], b[3]);
        *reinterpret_cast<uint4*>(d + 16) = make_uint4(b[4], b[5], b[6], b[7]);
    }
}

// ---------------- hybrid CSA-XNOR(alu) + IMMA(tensor) GEMM ----------------
__global__ void __launch_bounds__(512, 1) hybrid_gemm(
    const uint32_t* __restrict__ xT, const uint32_t* __restrict__ wT,
    const uint8_t* __restrict__ x8, const uint8_t* __restrict__ w8,
    const float* __restrict__ bias, float* __restrict__ out)
{
    extern __shared__ __align__(16) uint32_t sm[];
    const uint32_t smBase = smem_u32(sm);
    const int tid = threadIdx.x;
    const int mt  = blockIdx.x & 63;
    const int nt  = blockIdx.x >> 6;
    const int mBase = mt * TW;
    const int nBase = nt * TW;

    if (tid < 256) {
        // ============ XNOR group: k-words [0,96), CSA 8->4, u16x2 acc ============
        const int t  = tid;
        const int tx = t & 15;
        const int ty = t >> 4;

        auto loadX = [&](int s, int c) {
            #pragma unroll
            for (int k = 0; k < 4; k++) {
                const int ch  = t + k * 256;
                const int tsr = ch >> 9;
                const int rem = ch & 511;
                const int kw  = rem >> 5;
                const int nq  = rem & 31;
                const uint32_t* gsrc = tsr
                    ? (wT + (size_t)(c * CHUNK + kw) * ODIM  + nBase + nq * 4)
                    : (xT + (size_t)(c * CHUNK + kw) * NROWS + mBase + nq * 4);
                const uint32_t dst = smBase +
                    (uint32_t)((s * XST_WORDS + tsr * 2048 + kw * TW + nq * 4) * 4);
                CP_ASYNC16(dst, gsrc);
            }
        };

        // packed u16x2 accumulators: [row][colpair], lo = even col, hi = odd col
        uint32_t accP[8][4];
        #pragma unroll
        for (int r = 0; r < 8; r++)
            #pragma unroll
            for (int c = 0; c < 4; c++) accP[r][c] = 0;

        #pragma unroll
        for (int s = 0; s < 3; s++) { loadX(s, s); CP_COMMIT(); }

        #pragma unroll 1
        for (int c = 0; c < KITX; c++) {
            const int cl = c + 3;
            if (cl < KITX) loadX(cl & 3, cl);
            CP_COMMIT();
            CP_WAIT(3);
            BAR(1);

            const uint32_t* As = sm + (c & 3) * XST_WORDS;
            const uint32_t* Bs = As + 2048;

            #pragma unroll
            for (int g = 0; g < 2; g++) {
                const int kb = g * 8;
                #pragma unroll
                for (int ch2 = 0; ch2 < 2; ch2++) {     // column halves (4 cols)
                    uint32_t Bf[8][4];
                    #pragma unroll
                    for (int k = 0; k < 8; k++) {
                        uint4 u = *reinterpret_cast<const uint4*>(
                            Bs + (kb + k) * TW + tx * 8 + ch2 * 4);
                        Bf[k][0] = u.x; Bf[k][1] = u.y; Bf[k][2] = u.z; Bf[k][3] = u.w;
                    }
                    #pragma unroll
                    for (int rh = 0; rh < 2; rh++) {    // row halves (4 rows)
                        uint32_t Af[8][4];
                        #pragma unroll
                        for (int k = 0; k < 8; k++) {
                            uint4 u = *reinterpret_cast<const uint4*>(
                                As + (kb + k) * TW + ty * 8 + rh * 4);
                            Af[k][0] = u.x; Af[k][1] = u.y; Af[k][2] = u.z; Af[k][3] = u.w;
                        }
                        #pragma unroll
                        for (int r = 0; r < 4; r++) {
                            #pragma unroll
                            for (int cp = 0; cp < 2; cp++) {
                                uint32_t tt[2];
                                #pragma unroll
                                for (int h = 0; h < 2; h++) {
                                    const int cc = cp * 2 + h;
                                    const uint32_t x0 = Af[0][r] ^ Bf[0][cc];
                                    const uint32_t x1 = Af[1][r] ^ Bf[1][cc];
                                    const uint32_t x2 = Af[2][r] ^ Bf[2][cc];
                                    const uint32_t x3 = Af[3][r] ^ Bf[3][cc];
                                    const uint32_t x4 = Af[4][r] ^ Bf[4][cc];
                                    const uint32_t x5 = Af[5][r] ^ Bf[5][cc];
                                    const uint32_t x6 = Af[6][r] ^ Bf[6][cc];
                                    const uint32_t x7 = Af[7][r] ^ Bf[7][cc];
                                    const uint32_t s0 = xor3(x0, x1, x2);
                                    const uint32_t c0 = maj3(x0, x1, x2);
                                    const uint32_t s1 = xor3(x3, x4, x5);
                                    const uint32_t c1 = maj3(x3, x4, x5);
                                    const uint32_t s2 = x6 ^ x7;
                                    const uint32_t c2 = x6 & x7;
                                    const uint32_t S  = xor3(s0, s1, s2);
                                    const uint32_t C3 = maj3(s0, s1, s2);
                                    const uint32_t S2 = xor3(c0, c1, c2);
                                    const uint32_t C2 = maj3(c0, c1, c2);
                                    tt[h] = __popc(S)
                                          + 2 * (__popc(S2) + __popc(C3))
                                          + 4 * __popc(C2);
                                }
                                accP[rh * 4 + r][ch2 * 2 + cp] += tt[0] + (tt[1] << 16);
                            }
                        }
                    }
                }
            }
            BAR(1);
        }

        __syncthreads();   // join #1: IMMA group done; stages reusable
        __syncthreads();   // join #2: IMMA partials in smem [0,64K)

        // -------- epilogue: head + tail + bias --------
        const int rb = mBase + ty * 8;
        const int cb = nBase + tx * 8;
        const float4 bias0 = *reinterpret_cast<const float4*>(bias + cb);
        const float4 bias1 = *reinterpret_cast<const float4*>(bias + cb + 4);
        const int* smC = reinterpret_cast<const int*>(sm);

        #pragma unroll
        for (int r = 0; r < 8; r++) {
            int4 p0 = *reinterpret_cast<const int4*>(smC + (ty * 8 + r) * TW + tx * 8);
            int4 p1 = *reinterpret_cast<const int4*>(smC + (ty * 8 + r) * TW + tx * 8 + 4);
            const int c0 = (int)(accP[r][0] & 0xFFFF), c1 = (int)(accP[r][0] >> 16);
            const int c2 = (int)(accP[r][1] & 0xFFFF), c3 = (int)(accP[r][1] >> 16);
            const int c4 = (int)(accP[r][2] & 0xFFFF), c5 = (int)(accP[r][2] >> 16);
            const int c6 = (int)(accP[r][3] & 0xFFFF), c7 = (int)(accP[r][3] >> 16);
            float4 o0, o1;
            o0.x = (float)(KHEAD - 2 * c0 + p0.x) + bias0.x;
            o0.y = (float)(KHEAD - 2 * c1 + p0.y) + bias0.y;
            o0.z = (float)(KHEAD - 2 * c2 + p0.z) + bias0.z;
            o0.w = (float)(KHEAD - 2 * c3 + p0.w) + bias0.w;
            o1.x = (float)(KHEAD - 2 * c4 + p1.x) + bias1.x;
            o1.y = (float)(KHEAD - 2 * c5 + p1.y) + bias1.y;
            o1.z = (float)(KHEAD - 2 * c6 + p1.z) + bias1.z;
            o1.w = (float)(KHEAD - 2 * c7 + p1.w) + bias1.w;
            float* po = out + (size_t)(rb + r) * ODIM + cb;
            *reinterpret_cast<float4*>(po)     = o0;
            *reinterpret_cast<float4*>(po + 4) = o1;
        }
    } else {
        // ===================== IMMA group: s8 tail K=1024 =====================
        const int t2   = tid - 256;
        const int w2   = t2 >> 5;          // 0..7: 2(m) x 4(n)
        const int lane = t2 & 31;
        const int wm   = (w2 & 1) * 64;
        const int wn   = (w2 >> 1) * 32;

        auto loadI = [&](int s, int kit) {
            #pragma unroll
            for (int k = 0; k < 8; k++) {
                const int ch  = t2 + k * 256;      // 0..2047
                const int tsr = ch >> 10;
                const int rem = ch & 1023;
                const int row = rem >> 3;
                const int c16 = rem & 7;
                const uint8_t* gsrc = tsr
                    ? (w8 + (size_t)(nBase + row) * K8 + kit * 128 + c16 * 16)
                    : (x8 + (size_t)(mBase + row) * K8 + kit * 128 + c16 * 16);
                const uint32_t dst = smBase + IS_BASE + s * IST_BYTES + tsr * 16384
                    + row * 128 + (((uint32_t)(c16 * 16)) ^ ((row & 7) << 4));
                CP_ASYNC16(dst, gsrc);
            }
        };

        const int rA = wm + (lane & 7) + ((lane >> 3) & 1) * 8;
        const int cA = ((lane >> 4) & 1) * 16;
        const uint32_t swzA = (uint32_t)((rA & 7) << 4);
        const int rB = wn + (lane & 7) + ((lane >> 4) & 1) * 8;
        const int cB = ((lane >> 3) & 1) * 16;
        const uint32_t swzB = (uint32_t)((rB & 7) << 4);

        int acc[4][4][4];
        #pragma unroll
        for (int mi = 0; mi < 4; mi++)
            #pragma unroll
            for (int ni = 0; ni < 4; ni++)
                #pragma unroll
                for (int q = 0; q < 4; q++) acc[mi][ni][q] = 0;

        loadI(0, 0); CP_COMMIT();
        loadI(1, 1); CP_COMMIT();

        #pragma unroll 1
        for (int kit = 0; kit < KITI; kit++) {
            const int s = kit % 3;
            CP_WAIT(1);
            BAR(2);

            const uint32_t sA = smBase + IS_BASE + s * IST_BYTES + rA * 128;
            const uint32_t sB = smBase + IS_BASE + s * IST_BYTES + 16384 + rB * 128;

            #pragma unroll
            for (int ks = 0; ks < 4; ks++) {
                uint32_t aF[4][4];
                uint32_t bF[2][4];
                #pragma unroll
                for (int mi = 0; mi < 4; mi++)
                    ldsm4(aF[mi], sA + mi * (16 * 128) + (((uint32_t)(cA + ks * 32)) ^ swzA));
                #pragma unroll
                for (int np = 0; np < 2; np++)
                    ldsm4(bF[np], sB + np * (16 * 128) + (((uint32_t)(cB + ks * 32)) ^ swzB));
                #pragma unroll
                for (int ni = 0; ni < 4; ni++)
                    #pragma unroll
                    for (int mi = 0; mi < 4; mi++)
                        mma_s8(acc[mi][ni], aF[mi], bF[ni >> 1][(ni & 1) * 2],
                                                     bF[ni >> 1][(ni & 1) * 2 + 1]);
            }
            BAR(2);

            const int kl = kit + 2;
            if (kl < KITI) loadI(kl % 3, kl);
            CP_COMMIT();
        }

        __syncthreads();   // join #1: XNOR done reading its stages

        int* smC = reinterpret_cast<int*>(sm);
        const int colL = wn + (lane & 3) * 2;
        const int rowB = wm + (lane >> 2);
        #pragma unroll
        for (int mi = 0; mi < 4; mi++) {
            const int r0 = rowB + mi * 16;
            #pragma unroll
            for (int ni = 0; ni < 4; ni++) {
                *reinterpret_cast<int2*>(smC + r0 * TW + colL + ni * 8) =
                    make_int2(acc[mi][ni][0], acc[mi][ni][1]);
                *reinterpret_cast<int2*>(smC + (r0 + 8) * TW + colL + ni * 8) =
                    make_int2(acc[mi][ni][2], acc[mi][ni][3]);
            }
        }
        __syncthreads();   // join #2: partials visible to XNOR epilogue
    }
}

// ---------------- host ----------------
extern "C" void kernel_launch(void* const* d_in, const int* in_sizes, int n_in,
                              void* d_out, int out_size) {
    const float* x    = (const float*)d_in[0];
    const float* w    = (const float*)d_in[1];
    const float* bias = (const float*)d_in[2];
    float* out = (float*)d_out;

    void* pxT = nullptr; cudaGetSymbolAddress(&pxT, g_xT);
    void* pwT = nullptr; cudaGetSymbolAddress(&pwT, g_wT);
    void* px8 = nullptr; cudaGetSymbolAddress(&px8, g_x8);
    void* pw8 = nullptr; cudaGetSymbolAddress(&pw8, g_w8);

    pack_bits2<<<(KW * NROWS) / 256, 256>>>((const float4*)x, (uint32_t*)pxT,
                                            (uint8_t*)px8, 13);
    pack_bits2<<<(KW * ODIM) / 256, 256>>>((const float4*)w, (uint32_t*)pwT,
                                           (uint8_t*)pw8, 12);

    cudaFuncSetAttribute(hybrid_gemm, cudaFuncAttributeMaxDynamicSharedMemorySize,
                         SMEM_BYTES);

    const int grid = (NROWS / TW) * (ODIM / TW);   // 2048
    hybrid_gemm<<<grid, 512, SMEM_BYTES>>>((const uint32_t*)pxT, (const uint32_t*)pwT,
                                           (const uint8_t*)px8, (const uint8_t*)pw8,
                                           bias, out);
}